// round 8
// baseline (speedup 1.0000x reference)
#include <cuda_runtime.h>
#include <cuda_bf16.h>

// BinaryLutLayer: out[i] = (float)(int8) round_half_even( luts_float[i][addr_i] + 0.5 )
// addr_i = sum_b ((x[i][b] != 0) << b); N = 16384 rows, 14 bits, LUT row = 16384 floats.
//
// Latency-bound kernel (R4 ncu: DRAM 4.6%, issue 4.9%). This version removes
// the smem staging + barrier from the critical path (direct per-thread float2
// loads, 7x LDG.64 front-batched; rows are 8B-aligned since stride = 56 B)
// and spreads the grid to 128 CTAs so 128/148 SMs absorb the two dependent
// DRAM round-trips in parallel. (Resubmit of R6 — prior run died to a
// container infra failure, kernel never executed.)

#define NUM_BITS 14
#define LUT_SIZE 16384
#define N_OUT    16384
#define TPB      128

__global__ __launch_bounds__(TPB)
void binary_lut_kernel(const float* __restrict__ x,
                       const float* __restrict__ luts_float,
                       float* __restrict__ out)
{
    const int row = blockIdx.x * TPB + threadIdx.x;

    // 14 floats = 7 x float2, 8B-aligned (row * 56 bytes). All 7 loads are
    // independent -> front-batched by ptxas (MLP_p1 = 7), one DRAM round.
    const float2* __restrict__ p =
        (const float2*)(x + (size_t)row * NUM_BITS);

    float2 v[7];
    #pragma unroll
    for (int j = 0; j < 7; j++)
        v[j] = p[j];

    int addr = 0;
    #pragma unroll
    for (int j = 0; j < 7; j++) {
        addr |= (v[j].x != 0.0f) ? (1 << (2 * j))     : 0;
        addr |= (v[j].y != 0.0f) ? (1 << (2 * j + 1)) : 0;
    }

    // One scattered 4B gather per row (row stride = 64 KB), dependent on addr.
    const float lv = __ldg(luts_float + (size_t)row * LUT_SIZE + addr);

    // round-half-even (== jnp.round) on bit-identical fp32, int8 cast, float.
    out[row] = (float)(signed char)rintf(lv + 0.5f);
}

extern "C" void kernel_launch(void* const* d_in, const int* in_sizes, int n_in,
                              void* d_out, int out_size)
{
    const float* x          = (const float*)d_in[0];
    const float* luts_float = (const float*)d_in[1];
    // d_in[2] (luts_int) unused: device dtype after harness widening is
    // ambiguous; values are reproduced bit-exactly from luts_float.
    float* out = (float*)d_out;

    binary_lut_kernel<<<N_OUT / TPB, TPB>>>(x, luts_float, out);
}